// round 1
// baseline (speedup 1.0000x reference)
#include <cuda_runtime.h>
#include <math.h>

#define BATCH 8
#define DIM   256
#define HH    64
#define WW    64
#define MM    4096
#define QC    64
#define KC    16
#define VC    64
#define NHD   4
#define DKK   16
#define DVV   64
#define RR    23
#define PADR  11
#define EPS_BN 1e-5f

// ---------------- scratch (device globals: no allocations allowed) ----------
__device__ float g_q   [BATCH*QC*MM];   // BN'd q, layout [b][o=h*16+k][m]
__device__ float g_kraw[BATCH*KC*MM];   // raw k logits
__device__ float g_vbn [BATCH*VC*MM];   // BN'd v
__device__ float g_ksm [BATCH*KC*MM];   // softmax(k) over M
__device__ float g_lc  [BATCH*DKK*DVV]; // lambda_c[b][k][v]

// ---------------- K1: QKV GEMM + fused BN ----------------------------------
// per batch: Y[144,4096] = W[144,256] @ X[256,4096]
// grid (64 mtiles, 8 b), block 256.  tile = 144 o x 64 m.
__global__ __launch_bounds__(256) void k1_qkv(
    const float* __restrict__ x, const float* __restrict__ w,
    const float* __restrict__ qg, const float* __restrict__ qb,
    const float* __restrict__ qm, const float* __restrict__ qv,
    const float* __restrict__ vg, const float* __restrict__ vb,
    const float* __restrict__ vm, const float* __restrict__ vvr)
{
    __shared__ float Xs[32][64];
    __shared__ float Ws[32][144];
    const int b     = blockIdx.y;
    const int mtile = blockIdx.x * 64;
    const int tid   = threadIdx.x;
    const int mg    = tid & 15;   // 16 m-groups (4 m each)
    const int og    = tid >> 4;   // 16 o-groups (o = og + 16*i)

    float4 acc[9];
#pragma unroll
    for (int i = 0; i < 9; i++) acc[i] = make_float4(0.f, 0.f, 0.f, 0.f);

    const float* xb = x + (size_t)b * DIM * MM + mtile;

    for (int c0 = 0; c0 < DIM; c0 += 32) {
        // load X tile [32 c][64 m], 8 floats/thread
        {
            int L  = tid * 8;
            int cc = L >> 6;
            int ml = L & 63;
            const float* src = xb + (size_t)(c0 + cc) * MM + ml;
            *reinterpret_cast<float4*>(&Xs[cc][ml])     = *reinterpret_cast<const float4*>(src);
            *reinterpret_cast<float4*>(&Xs[cc][ml + 4]) = *reinterpret_cast<const float4*>(src + 4);
        }
        // load W tile [32 c][144 o] (transposed from (o,c) row-major)
        for (int idx = tid; idx < 32 * 144; idx += 256) {
            int cc = idx / 144;
            int o  = idx - cc * 144;
            Ws[cc][o] = w[o * DIM + c0 + cc];
        }
        __syncthreads();
#pragma unroll
        for (int cc = 0; cc < 32; cc++) {
            float4 xv = *reinterpret_cast<const float4*>(&Xs[cc][mg * 4]);
#pragma unroll
            for (int i = 0; i < 9; i++) {
                float wv = Ws[cc][og + 16 * i];
                acc[i].x += wv * xv.x;
                acc[i].y += wv * xv.y;
                acc[i].z += wv * xv.z;
                acc[i].w += wv * xv.w;
            }
        }
        __syncthreads();
    }

    const int m = mtile + mg * 4;
#pragma unroll
    for (int i = 0; i < 9; i++) {
        int o = og + 16 * i;
        float4 v = acc[i];
        if (o < QC) {
            float s  = qg[o] * rsqrtf(qv[o] + EPS_BN);
            float sh = qb[o] - qm[o] * s;
            v.x = v.x * s + sh; v.y = v.y * s + sh;
            v.z = v.z * s + sh; v.w = v.w * s + sh;
            *reinterpret_cast<float4*>(&g_q[((size_t)b * QC + o) * MM + m]) = v;
        } else if (o < QC + KC) {
            *reinterpret_cast<float4*>(&g_kraw[((size_t)b * KC + (o - QC)) * MM + m]) = v;
        } else {
            int ov   = o - QC - KC;
            float s  = vg[ov] * rsqrtf(vvr[ov] + EPS_BN);
            float sh = vb[ov] - vm[ov] * s;
            v.x = v.x * s + sh; v.y = v.y * s + sh;
            v.z = v.z * s + sh; v.w = v.w * s + sh;
            *reinterpret_cast<float4*>(&g_vbn[((size_t)b * VC + ov) * MM + m]) = v;
        }
    }
}

// ---------------- K2: softmax over M per (b,k) ------------------------------
// grid (16 k, 8 b), block 256
__global__ __launch_bounds__(256) void k2_softmax()
{
    const int b = blockIdx.y, k = blockIdx.x;
    const float* src = g_kraw + ((size_t)b * KC + k) * MM;
    float*       dst = g_ksm  + ((size_t)b * KC + k) * MM;
    const int tid = threadIdx.x;
    __shared__ float red[33];

    // --- max ---
    float mx = -1e30f;
    for (int m = tid; m < MM; m += 256) mx = fmaxf(mx, src[m]);
#pragma unroll
    for (int o = 16; o > 0; o >>= 1) mx = fmaxf(mx, __shfl_xor_sync(0xffffffffu, mx, o));
    if ((tid & 31) == 0) red[tid >> 5] = mx;
    __syncthreads();
    if (tid < 32) {
        float v = (tid < 8) ? red[tid] : -1e30f;
#pragma unroll
        for (int o = 4; o > 0; o >>= 1) v = fmaxf(v, __shfl_xor_sync(0xffffffffu, v, o));
        if (tid == 0) red[0] = v;
    }
    __syncthreads();
    mx = red[0];
    __syncthreads();

    // --- sum exp ---
    float sm = 0.f;
    for (int m = tid; m < MM; m += 256) sm += expf(src[m] - mx);
#pragma unroll
    for (int o = 16; o > 0; o >>= 1) sm += __shfl_xor_sync(0xffffffffu, sm, o);
    if ((tid & 31) == 0) red[tid >> 5] = sm;
    __syncthreads();
    if (tid < 32) {
        float v = (tid < 8) ? red[tid] : 0.f;
#pragma unroll
        for (int o = 4; o > 0; o >>= 1) v += __shfl_xor_sync(0xffffffffu, v, o);
        if (tid == 0) red[32] = 1.f / v;
    }
    __syncthreads();
    const float inv = red[32];

    for (int m = tid; m < MM; m += 256) dst[m] = expf(src[m] - mx) * inv;
}

// ---------------- K3: lambda_c[b,k,v] = sum_m ksm[b,k,m] * vbn[b,v,m] -------
// grid (64 v, 8 b), block 256
__global__ __launch_bounds__(256) void k3_lambdac()
{
    const int b = blockIdx.y, v = blockIdx.x;
    const int tid = threadIdx.x;
    const float* vp = g_vbn + ((size_t)b * VC + v) * MM;
    const float* kp = g_ksm + (size_t)b * KC * MM;

    float acc[16];
#pragma unroll
    for (int k = 0; k < 16; k++) acc[k] = 0.f;

    for (int m = tid; m < MM; m += 256) {
        float vv = vp[m];
#pragma unroll
        for (int k = 0; k < 16; k++) acc[k] += kp[(size_t)k * MM + m] * vv;
    }

    __shared__ float part[16][9];
    const int lane = tid & 31, wid = tid >> 5;
#pragma unroll
    for (int k = 0; k < 16; k++) {
        float s = acc[k];
#pragma unroll
        for (int o = 16; o > 0; o >>= 1) s += __shfl_xor_sync(0xffffffffu, s, o);
        if (lane == 0) part[k][wid] = s;
    }
    __syncthreads();
    if (tid < 16) {
        float s = 0.f;
#pragma unroll
        for (int w2 = 0; w2 < 8; w2++) s += part[tid][w2];
        g_lc[((size_t)b * DKK + tid) * DVV + v] = s;
    }
}

// ---------------- K4: fused 23x23 conv + q-contraction ----------------------
// out[b, h*64+v, m] = sum_k q[b,h,k,m] * (lc[b,k,v] + b_lambda[k] + conv_k(vbn[b,v])[m])
// grid (4 ytiles, 64 v, 8 b), block 256 (8 warps; warp = 1 row, lane = 2 px)
__device__ __forceinline__ unsigned long long pack2(float f)
{
    unsigned long long r;
    unsigned u = __float_as_uint(f);
    asm("mov.b64 %0, {%1,%2};" : "=l"(r) : "r"(u), "r"(u));
    return r;
}
#define FMA2(a, w, v) asm("fma.rn.f32x2 %0, %1, %2, %0;" : "+l"(a) : "l"(w), "l"(v))

__global__ __launch_bounds__(256) void k4_main(
    const float* __restrict__ wl, const float* __restrict__ bl,
    float* __restrict__ out)
{
    __shared__ float s_img[38 * 88];                 // 16-row tile + 11 halo, stride 88
    __shared__ __align__(16) float s_w[RR * RR * 16]; // [dy][dx][k], k contiguous
    __shared__ float s_lam[16];

    const int ytile = blockIdx.x;   // 0..3
    const int v     = blockIdx.y;   // 0..63
    const int b     = blockIdx.z;   // 0..7
    const int tid   = threadIdx.x;

    // weights reordered so (k,k+1) pairs are adjacent 64-bit words
    for (int idx = tid; idx < RR * RR * 16; idx += 256) {
        int k = idx & 15;
        int t = idx >> 4;
        s_w[idx] = wl[k * (RR * RR) + t];
    }
    if (tid < 16)
        s_lam[tid] = g_lc[((size_t)b * DKK + tid) * DVV + v] + bl[tid];

    // padded image tile
    const float* vp = g_vbn + ((size_t)b * VC + v) * MM;
    const int y0 = ytile * 16;
    for (int idx = tid; idx < 38 * 88; idx += 256) {
        int r  = idx / 88;
        int cc = idx - r * 88;
        int gy = y0 + r - PADR;
        int gx = cc - PADR;
        float val = 0.f;
        if (gy >= 0 && gy < HH && gx >= 0 && gx < WW) val = vp[gy * WW + gx];
        s_img[idx] = val;
    }
    __syncthreads();

    const int lane = tid & 31, wid = tid >> 5;
    const float* qb_ = g_q + (size_t)b * QC * MM;
    float*       ob  = out + (size_t)b * DIM * MM;

#pragma unroll 1
    for (int pass = 0; pass < 2; pass++) {
        const int yl = pass * 8 + wid;   // local row 0..15
        const int x0 = lane * 2;         // two adjacent pixels x0, x0+1

        unsigned long long a0[8], a1[8]; // 8 k-pairs x 2 pixels, packed f32x2
#pragma unroll
        for (int p = 0; p < 8; p++) { a0[p] = 0ull; a1[p] = 0ull; }

#pragma unroll 1
        for (int dy = 0; dy < RR; dy++) {
            const float*   rowp = &s_img[(yl + dy) * 88 + x0];
            const double2* wp   = reinterpret_cast<const double2*>(&s_w[dy * RR * 16]);
            float v0 = rowp[0];
#pragma unroll
            for (int dx = 0; dx < RR; dx++) {
                float v1 = rowp[dx + 1];
                unsigned long long vv0 = pack2(v0);
                unsigned long long vv1 = pack2(v1);
                double2 wA = wp[dx * 4 + 0];
                double2 wB = wp[dx * 4 + 1];
                double2 wC = wp[dx * 4 + 2];
                double2 wD = wp[dx * 4 + 3];
                unsigned long long w0 = __double_as_longlong(wA.x);
                unsigned long long w1 = __double_as_longlong(wA.y);
                unsigned long long w2 = __double_as_longlong(wB.x);
                unsigned long long w3 = __double_as_longlong(wB.y);
                unsigned long long w4 = __double_as_longlong(wC.x);
                unsigned long long w5 = __double_as_longlong(wC.y);
                unsigned long long w6 = __double_as_longlong(wD.x);
                unsigned long long w7 = __double_as_longlong(wD.y);
                FMA2(a0[0], w0, vv0); FMA2(a1[0], w0, vv1);
                FMA2(a0[1], w1, vv0); FMA2(a1[1], w1, vv1);
                FMA2(a0[2], w2, vv0); FMA2(a1[2], w2, vv1);
                FMA2(a0[3], w3, vv0); FMA2(a1[3], w3, vv1);
                FMA2(a0[4], w4, vv0); FMA2(a1[4], w4, vv1);
                FMA2(a0[5], w5, vv0); FMA2(a1[5], w5, vv1);
                FMA2(a0[6], w6, vv0); FMA2(a1[6], w6, vv1);
                FMA2(a0[7], w7, vv0); FMA2(a1[7], w7, vv1);
                v0 = v1;
            }
        }

        // epilogue: unpack conv accumulators, add lambda_c + b_lambda, contract with q
        const int y  = y0 + yl;
        const int m0 = y * WW + x0;
        float lam0[16], lam1[16];
#pragma unroll
        for (int p = 0; p < 8; p++) {
            unsigned lo, hi;
            asm("mov.b64 {%0,%1}, %2;" : "=r"(lo), "=r"(hi) : "l"(a0[p]));
            lam0[2 * p]     = __uint_as_float(lo) + s_lam[2 * p];
            lam0[2 * p + 1] = __uint_as_float(hi) + s_lam[2 * p + 1];
            asm("mov.b64 {%0,%1}, %2;" : "=r"(lo), "=r"(hi) : "l"(a1[p]));
            lam1[2 * p]     = __uint_as_float(lo) + s_lam[2 * p];
            lam1[2 * p + 1] = __uint_as_float(hi) + s_lam[2 * p + 1];
        }
#pragma unroll
        for (int h = 0; h < NHD; h++) {
            float s0 = 0.f, s1 = 0.f;
#pragma unroll
            for (int k = 0; k < 16; k++) {
                const float* qp = qb_ + (size_t)(h * 16 + k) * MM + m0;
                s0 += qp[0] * lam0[k];
                s1 += qp[1] * lam1[k];
            }
            *reinterpret_cast<float2*>(&ob[(size_t)(h * DVV + v) * MM + m0]) =
                make_float2(s0, s1);
        }
    }
}

// ---------------- launch ----------------------------------------------------
extern "C" void kernel_launch(void* const* d_in, const int* in_sizes, int n_in,
                              void* d_out, int out_size)
{
    const float* x    = (const float*)d_in[0];
    const float* wq   = (const float*)d_in[1];
    const float* qg   = (const float*)d_in[2];
    const float* qb   = (const float*)d_in[3];
    const float* qm   = (const float*)d_in[4];
    const float* qv   = (const float*)d_in[5];
    const float* vg   = (const float*)d_in[6];
    const float* vb   = (const float*)d_in[7];
    const float* vm   = (const float*)d_in[8];
    const float* vvr  = (const float*)d_in[9];
    const float* wl   = (const float*)d_in[10];
    const float* bl   = (const float*)d_in[11];
    float*       out  = (float*)d_out;

    dim3 g1(MM / 64, BATCH);
    k1_qkv<<<g1, 256>>>(x, wq, qg, qb, qm, qv, vg, vb, vm, vvr);

    dim3 g2(KC, BATCH);
    k2_softmax<<<g2, 256>>>();

    dim3 g3(DVV, BATCH);
    k3_lambdac<<<g3, 256>>>();

    dim3 g4(4, DVV, BATCH);
    k4_main<<<g4, 256>>>(wl, bl, out);
}

// round 2
// speedup vs baseline: 1.0106x; 1.0106x over previous
#include <cuda_runtime.h>
#include <math.h>

#define BATCH 8
#define DIM   256
#define HH    64
#define WW    64
#define MM    4096
#define QC    64
#define KC    16
#define VC    64
#define NHD   4
#define DKK   16
#define DVV   64
#define RR    23
#define PADR  11
#define EPS_BN 1e-5f

#define SIMS  89   // s_img row stride (odd offset => fewer bank conflicts)

// ---------------- scratch (device globals: no allocations allowed) ----------
__device__ float g_q   [BATCH*QC*MM];   // BN'd q, layout [b][o=h*16+k][m]
__device__ float g_kraw[BATCH*KC*MM];   // raw k logits
__device__ float g_vbn [BATCH*VC*MM];   // BN'd v
__device__ float g_ksm [BATCH*KC*MM];   // softmax(k) over M
__device__ float g_lc  [BATCH*DKK*DVV]; // lambda_c[b][k][v]

// ---------------- packed f32x2 helpers --------------------------------------
__device__ __forceinline__ unsigned long long pack2(float f)
{
    unsigned long long r;
    unsigned u = __float_as_uint(f);
    asm("mov.b64 %0, {%1,%2};" : "=l"(r) : "r"(u), "r"(u));
    return r;
}
__device__ __forceinline__ unsigned long long packab(float a, float b)
{
    unsigned long long r;
    asm("mov.b64 %0, {%1,%2};" : "=l"(r)
        : "r"(__float_as_uint(a)), "r"(__float_as_uint(b)));
    return r;
}
#define FMA2(a, w, v) asm("fma.rn.f32x2 %0, %1, %2, %0;" : "+l"(a) : "l"(w), "l"(v))

// ---------------- K1: QKV GEMM + fused BN (f32x2 inner) ---------------------
// per batch: Y[144,4096] = W[144,256] @ X[256,4096]
// grid (64 mtiles, 8 b), block 256.  tile = 144 o x 64 m.
__global__ __launch_bounds__(256) void k1_qkv(
    const float* __restrict__ x, const float* __restrict__ w,
    const float* __restrict__ qg, const float* __restrict__ qb,
    const float* __restrict__ qm, const float* __restrict__ qv,
    const float* __restrict__ vg, const float* __restrict__ vb,
    const float* __restrict__ vm, const float* __restrict__ vvr)
{
    __shared__ float Xs[32][64];
    __shared__ float Ws[32][144];
    const int b     = blockIdx.y;
    const int mtile = blockIdx.x * 64;
    const int tid   = threadIdx.x;
    const int mg    = tid & 15;   // 16 m-groups (4 m each)
    const int og    = tid >> 4;   // 16 o-groups (o = og + 16*i)

    unsigned long long a01[9], a23[9];
#pragma unroll
    for (int i = 0; i < 9; i++) { a01[i] = 0ull; a23[i] = 0ull; }

    const float* xb = x + (size_t)b * DIM * MM + mtile;

    for (int c0 = 0; c0 < DIM; c0 += 32) {
        {
            int L  = tid * 8;
            int cc = L >> 6;
            int ml = L & 63;
            const float* src = xb + (size_t)(c0 + cc) * MM + ml;
            *reinterpret_cast<float4*>(&Xs[cc][ml])     = *reinterpret_cast<const float4*>(src);
            *reinterpret_cast<float4*>(&Xs[cc][ml + 4]) = *reinterpret_cast<const float4*>(src + 4);
        }
        for (int idx = tid; idx < 32 * 144; idx += 256) {
            int cc = idx / 144;
            int o  = idx - cc * 144;
            Ws[cc][o] = w[o * DIM + c0 + cc];
        }
        __syncthreads();
#pragma unroll
        for (int cc = 0; cc < 32; cc++) {
            float4 xv = *reinterpret_cast<const float4*>(&Xs[cc][mg * 4]);
            unsigned long long xv01 = packab(xv.x, xv.y);
            unsigned long long xv23 = packab(xv.z, xv.w);
#pragma unroll
            for (int i = 0; i < 9; i++) {
                unsigned long long wv = pack2(Ws[cc][og + 16 * i]);
                FMA2(a01[i], wv, xv01);
                FMA2(a23[i], wv, xv23);
            }
        }
        __syncthreads();
    }

    const int m = mtile + mg * 4;
#pragma unroll
    for (int i = 0; i < 9; i++) {
        int o = og + 16 * i;
        float4 v;
        unsigned lo, hi;
        asm("mov.b64 {%0,%1}, %2;" : "=r"(lo), "=r"(hi) : "l"(a01[i]));
        v.x = __uint_as_float(lo); v.y = __uint_as_float(hi);
        asm("mov.b64 {%0,%1}, %2;" : "=r"(lo), "=r"(hi) : "l"(a23[i]));
        v.z = __uint_as_float(lo); v.w = __uint_as_float(hi);
        if (o < QC) {
            float s  = qg[o] * rsqrtf(qv[o] + EPS_BN);
            float sh = qb[o] - qm[o] * s;
            v.x = v.x * s + sh; v.y = v.y * s + sh;
            v.z = v.z * s + sh; v.w = v.w * s + sh;
            *reinterpret_cast<float4*>(&g_q[((size_t)b * QC + o) * MM + m]) = v;
        } else if (o < QC + KC) {
            *reinterpret_cast<float4*>(&g_kraw[((size_t)b * KC + (o - QC)) * MM + m]) = v;
        } else {
            int ov   = o - QC - KC;
            float s  = vg[ov] * rsqrtf(vvr[ov] + EPS_BN);
            float sh = vb[ov] - vm[ov] * s;
            v.x = v.x * s + sh; v.y = v.y * s + sh;
            v.z = v.z * s + sh; v.w = v.w * s + sh;
            *reinterpret_cast<float4*>(&g_vbn[((size_t)b * VC + ov) * MM + m]) = v;
        }
    }
}

// ---------------- K2: softmax over M per (b,k) ------------------------------
__global__ __launch_bounds__(256) void k2_softmax()
{
    const int b = blockIdx.y, k = blockIdx.x;
    const float* src = g_kraw + ((size_t)b * KC + k) * MM;
    float*       dst = g_ksm  + ((size_t)b * KC + k) * MM;
    const int tid = threadIdx.x;
    __shared__ float red[33];

    float mx = -1e30f;
    for (int m = tid; m < MM; m += 256) mx = fmaxf(mx, src[m]);
#pragma unroll
    for (int o = 16; o > 0; o >>= 1) mx = fmaxf(mx, __shfl_xor_sync(0xffffffffu, mx, o));
    if ((tid & 31) == 0) red[tid >> 5] = mx;
    __syncthreads();
    if (tid < 32) {
        float v = (tid < 8) ? red[tid] : -1e30f;
#pragma unroll
        for (int o = 4; o > 0; o >>= 1) v = fmaxf(v, __shfl_xor_sync(0xffffffffu, v, o));
        if (tid == 0) red[0] = v;
    }
    __syncthreads();
    mx = red[0];
    __syncthreads();

    float sm = 0.f;
    for (int m = tid; m < MM; m += 256) sm += expf(src[m] - mx);
#pragma unroll
    for (int o = 16; o > 0; o >>= 1) sm += __shfl_xor_sync(0xffffffffu, sm, o);
    if ((tid & 31) == 0) red[tid >> 5] = sm;
    __syncthreads();
    if (tid < 32) {
        float v = (tid < 8) ? red[tid] : 0.f;
#pragma unroll
        for (int o = 4; o > 0; o >>= 1) v += __shfl_xor_sync(0xffffffffu, v, o);
        if (tid == 0) red[32] = 1.f / v;
    }
    __syncthreads();
    const float inv = red[32];

    for (int m = tid; m < MM; m += 256) dst[m] = expf(src[m] - mx) * inv;
}

// ---------------- K3: lambda_c[b,k,v] = sum_m ksm[b,k,m] * vbn[b,v,m] -------
__global__ __launch_bounds__(256) void k3_lambdac()
{
    const int b = blockIdx.y, v = blockIdx.x;
    const int tid = threadIdx.x;
    const float* vp = g_vbn + ((size_t)b * VC + v) * MM;
    const float* kp = g_ksm + (size_t)b * KC * MM;

    float acc[16];
#pragma unroll
    for (int k = 0; k < 16; k++) acc[k] = 0.f;

    for (int m = tid; m < MM; m += 256) {
        float vv = vp[m];
#pragma unroll
        for (int k = 0; k < 16; k++) acc[k] += kp[(size_t)k * MM + m] * vv;
    }

    __shared__ float part[16][9];
    const int lane = tid & 31, wid = tid >> 5;
#pragma unroll
    for (int k = 0; k < 16; k++) {
        float s = acc[k];
#pragma unroll
        for (int o = 16; o > 0; o >>= 1) s += __shfl_xor_sync(0xffffffffu, s, o);
        if (lane == 0) part[k][wid] = s;
    }
    __syncthreads();
    if (tid < 16) {
        float s = 0.f;
#pragma unroll
        for (int w2 = 0; w2 < 8; w2++) s += part[tid][w2];
        g_lc[((size_t)b * DKK + tid) * DVV + v] = s;
    }
}

// ---------------- K4: fused 23x23 conv + q-contraction ----------------------
// 4 pixels/thread: warp covers 2 rows x 64 cols; block (8 warps) covers 16 rows.
// grid (4 ytiles, 64 v, 8 b), block 256.
__global__ __launch_bounds__(256, 2) void k4_main(
    const float* __restrict__ wl, const float* __restrict__ bl,
    float* __restrict__ out)
{
    __shared__ float s_img[38 * SIMS];                // 16-row tile + 22 halo
    __shared__ __align__(16) float s_w[RR * RR * 16]; // [dy][dx][k], k contiguous
    __shared__ float s_lam[16];

    const int ytile = blockIdx.x;   // 0..3
    const int v     = blockIdx.y;   // 0..63
    const int b     = blockIdx.z;   // 0..7
    const int tid   = threadIdx.x;

    for (int idx = tid; idx < RR * RR * 16; idx += 256) {
        int k = idx & 15;
        int t = idx >> 4;
        s_w[idx] = wl[k * (RR * RR) + t];
    }
    if (tid < 16)
        s_lam[tid] = g_lc[((size_t)b * DKK + tid) * DVV + v] + bl[tid];

    const float* vp = g_vbn + ((size_t)b * VC + v) * MM;
    const int y0 = ytile * 16;
    for (int idx = tid; idx < 38 * SIMS; idx += 256) {
        int r  = idx / SIMS;
        int cc = idx - r * SIMS;
        int gy = y0 + r - PADR;
        int gx = cc - PADR;
        float val = 0.f;
        if (gy >= 0 && gy < HH && gx >= 0 && gx < WW) val = vp[gy * WW + gx];
        s_img[idx] = val;
    }
    __syncthreads();

    const int lane = tid & 31, wid = tid >> 5;
    const int yl = wid * 2 + (lane >> 4);    // local row 0..15
    const int x0 = (lane & 15) * 4;          // 4 adjacent pixels x0..x0+3

    unsigned long long a0[8], a1[8], a2[8], a3[8];
#pragma unroll
    for (int p = 0; p < 8; p++) { a0[p] = 0ull; a1[p] = 0ull; a2[p] = 0ull; a3[p] = 0ull; }

#pragma unroll 1
    for (int dy = 0; dy < RR; dy++) {
        const float*   rowp = &s_img[(yl + dy) * SIMS + x0];
        const double2* wp   = reinterpret_cast<const double2*>(&s_w[dy * RR * 16]);
        unsigned long long vv0 = pack2(rowp[0]);
        unsigned long long vv1 = pack2(rowp[1]);
        unsigned long long vv2 = pack2(rowp[2]);
        unsigned long long vv3 = pack2(rowp[3]);
#pragma unroll
        for (int dx = 0; dx < RR; dx++) {
            unsigned long long vnew = pack2(rowp[dx + 4]);
            double2 wA = wp[dx * 4 + 0];
            double2 wB = wp[dx * 4 + 1];
            double2 wC = wp[dx * 4 + 2];
            double2 wD = wp[dx * 4 + 3];
            unsigned long long w0 = __double_as_longlong(wA.x);
            unsigned long long w1 = __double_as_longlong(wA.y);
            unsigned long long w2 = __double_as_longlong(wB.x);
            unsigned long long w3 = __double_as_longlong(wB.y);
            unsigned long long w4 = __double_as_longlong(wC.x);
            unsigned long long w5 = __double_as_longlong(wC.y);
            unsigned long long w6 = __double_as_longlong(wD.x);
            unsigned long long w7 = __double_as_longlong(wD.y);
            FMA2(a0[0], w0, vv0); FMA2(a1[0], w0, vv1); FMA2(a2[0], w0, vv2); FMA2(a3[0], w0, vv3);
            FMA2(a0[1], w1, vv0); FMA2(a1[1], w1, vv1); FMA2(a2[1], w1, vv2); FMA2(a3[1], w1, vv3);
            FMA2(a0[2], w2, vv0); FMA2(a1[2], w2, vv1); FMA2(a2[2], w2, vv2); FMA2(a3[2], w2, vv3);
            FMA2(a0[3], w3, vv0); FMA2(a1[3], w3, vv1); FMA2(a2[3], w3, vv2); FMA2(a3[3], w3, vv3);
            FMA2(a0[4], w4, vv0); FMA2(a1[4], w4, vv1); FMA2(a2[4], w4, vv2); FMA2(a3[4], w4, vv3);
            FMA2(a0[5], w5, vv0); FMA2(a1[5], w5, vv1); FMA2(a2[5], w5, vv2); FMA2(a3[5], w5, vv3);
            FMA2(a0[6], w6, vv0); FMA2(a1[6], w6, vv1); FMA2(a2[6], w6, vv2); FMA2(a3[6], w6, vv3);
            FMA2(a0[7], w7, vv0); FMA2(a1[7], w7, vv1); FMA2(a2[7], w7, vv2); FMA2(a3[7], w7, vv3);
            vv0 = vv1; vv1 = vv2; vv2 = vv3; vv3 = vnew;
        }
    }

    // epilogue: unpack conv accumulators, add lambda_c + b_lambda, contract with q
    float lam0[16], lam1[16], lam2[16], lam3[16];
#pragma unroll
    for (int p = 0; p < 8; p++) {
        unsigned lo, hi;
        asm("mov.b64 {%0,%1}, %2;" : "=r"(lo), "=r"(hi) : "l"(a0[p]));
        lam0[2*p] = __uint_as_float(lo) + s_lam[2*p]; lam0[2*p+1] = __uint_as_float(hi) + s_lam[2*p+1];
        asm("mov.b64 {%0,%1}, %2;" : "=r"(lo), "=r"(hi) : "l"(a1[p]));
        lam1[2*p] = __uint_as_float(lo) + s_lam[2*p]; lam1[2*p+1] = __uint_as_float(hi) + s_lam[2*p+1];
        asm("mov.b64 {%0,%1}, %2;" : "=r"(lo), "=r"(hi) : "l"(a2[p]));
        lam2[2*p] = __uint_as_float(lo) + s_lam[2*p]; lam2[2*p+1] = __uint_as_float(hi) + s_lam[2*p+1];
        asm("mov.b64 {%0,%1}, %2;" : "=r"(lo), "=r"(hi) : "l"(a3[p]));
        lam3[2*p] = __uint_as_float(lo) + s_lam[2*p]; lam3[2*p+1] = __uint_as_float(hi) + s_lam[2*p+1];
    }

    const int m0 = (y0 + yl) * WW + x0;
    const float* qb_ = g_q + (size_t)b * QC * MM;
    float*       ob  = out + (size_t)b * DIM * MM;
#pragma unroll
    for (int h = 0; h < NHD; h++) {
        float4 s = make_float4(0.f, 0.f, 0.f, 0.f);
#pragma unroll
        for (int k = 0; k < 16; k++) {
            float4 qv = *reinterpret_cast<const float4*>(qb_ + (size_t)(h * 16 + k) * MM + m0);
            s.x += qv.x * lam0[k];
            s.y += qv.y * lam1[k];
            s.z += qv.z * lam2[k];
            s.w += qv.w * lam3[k];
        }
        *reinterpret_cast<float4*>(&ob[(size_t)(h * DVV + v) * MM + m0]) = s;
    }
}

// ---------------- launch ----------------------------------------------------
extern "C" void kernel_launch(void* const* d_in, const int* in_sizes, int n_in,
                              void* d_out, int out_size)
{
    const float* x    = (const float*)d_in[0];
    const float* wq   = (const float*)d_in[1];
    const float* qg   = (const float*)d_in[2];
    const float* qb   = (const float*)d_in[3];
    const float* qm   = (const float*)d_in[4];
    const float* qv   = (const float*)d_in[5];
    const float* vg   = (const float*)d_in[6];
    const float* vb   = (const float*)d_in[7];
    const float* vm   = (const float*)d_in[8];
    const float* vvr  = (const float*)d_in[9];
    const float* wl   = (const float*)d_in[10];
    const float* bl   = (const float*)d_in[11];
    float*       out  = (float*)d_out;

    dim3 g1(MM / 64, BATCH);
    k1_qkv<<<g1, 256>>>(x, wq, qg, qb, qm, qv, vg, vb, vm, vvr);

    dim3 g2(KC, BATCH);
    k2_softmax<<<g2, 256>>>();

    dim3 g3(DVV, BATCH);
    k3_lambdac<<<g3, 256>>>();

    dim3 g4(4, DVV, BATCH);
    k4_main<<<g4, 256>>>(wl, bl, out);
}

// round 3
// speedup vs baseline: 1.0108x; 1.0002x over previous
#include <cuda_runtime.h>
#include <math.h>

#define BATCH 8
#define DIM   256
#define HH    64
#define WW    64
#define MM    4096
#define QC    64
#define KC    16
#define VC    64
#define NHD   4
#define DKK   16
#define DVV   64
#define RR    23
#define PADR  11
#define EPS_BN 1e-5f

#define SIMS  89   // s_img row stride (odd offset => fewer bank conflicts)

// ---------------- scratch (device globals: no allocations allowed) ----------
__device__ float g_q   [BATCH*QC*MM];   // BN'd q, layout [b][o=h*16+k][m]
__device__ float g_kraw[BATCH*KC*MM];   // raw k logits
__device__ float g_vbn [BATCH*VC*MM];   // BN'd v
__device__ float g_ksm [BATCH*KC*MM];   // softmax(k) over M
__device__ float g_lc  [BATCH*DKK*DVV]; // lambda_c[b][k][v]

// ---------------- packed f32x2 helpers --------------------------------------
__device__ __forceinline__ unsigned long long pack2(float f)
{
    unsigned long long r;
    unsigned u = __float_as_uint(f);
    asm("mov.b64 %0, {%1,%2};" : "=l"(r) : "r"(u), "r"(u));
    return r;
}
__device__ __forceinline__ unsigned long long packab(float a, float b)
{
    unsigned long long r;
    asm("mov.b64 %0, {%1,%2};" : "=l"(r)
        : "r"(__float_as_uint(a)), "r"(__float_as_uint(b)));
    return r;
}
#define FMA2(a, w, v) asm("fma.rn.f32x2 %0, %1, %2, %0;" : "+l"(a) : "l"(w), "l"(v))

// ---------------- K1: QKV GEMM + fused BN (f32x2 inner) ---------------------
// per batch: Y[144,4096] = W[144,256] @ X[256,4096]
// grid (64 mtiles, 8 b), block 256.  tile = 144 o x 64 m.
__global__ __launch_bounds__(256) void k1_qkv(
    const float* __restrict__ x, const float* __restrict__ w,
    const float* __restrict__ qg, const float* __restrict__ qb,
    const float* __restrict__ qm, const float* __restrict__ qv,
    const float* __restrict__ vg, const float* __restrict__ vb,
    const float* __restrict__ vm, const float* __restrict__ vvr)
{
    __shared__ float Xs[32][64];
    __shared__ float Ws[32][144];
    const int b     = blockIdx.y;
    const int mtile = blockIdx.x * 64;
    const int tid   = threadIdx.x;
    const int mg    = tid & 15;   // 16 m-groups (4 m each)
    const int og    = tid >> 4;   // 16 o-groups (o = og + 16*i)

    unsigned long long a01[9], a23[9];
#pragma unroll
    for (int i = 0; i < 9; i++) { a01[i] = 0ull; a23[i] = 0ull; }

    const float* xb = x + (size_t)b * DIM * MM + mtile;

    for (int c0 = 0; c0 < DIM; c0 += 32) {
        {
            int L  = tid * 8;
            int cc = L >> 6;
            int ml = L & 63;
            const float* src = xb + (size_t)(c0 + cc) * MM + ml;
            *reinterpret_cast<float4*>(&Xs[cc][ml])     = *reinterpret_cast<const float4*>(src);
            *reinterpret_cast<float4*>(&Xs[cc][ml + 4]) = *reinterpret_cast<const float4*>(src + 4);
        }
        for (int idx = tid; idx < 32 * 144; idx += 256) {
            int cc = idx / 144;
            int o  = idx - cc * 144;
            Ws[cc][o] = w[o * DIM + c0 + cc];
        }
        __syncthreads();
#pragma unroll
        for (int cc = 0; cc < 32; cc++) {
            float4 xv = *reinterpret_cast<const float4*>(&Xs[cc][mg * 4]);
            unsigned long long xv01 = packab(xv.x, xv.y);
            unsigned long long xv23 = packab(xv.z, xv.w);
#pragma unroll
            for (int i = 0; i < 9; i++) {
                unsigned long long wv = pack2(Ws[cc][og + 16 * i]);
                FMA2(a01[i], wv, xv01);
                FMA2(a23[i], wv, xv23);
            }
        }
        __syncthreads();
    }

    const int m = mtile + mg * 4;
#pragma unroll
    for (int i = 0; i < 9; i++) {
        int o = og + 16 * i;
        float4 v;
        unsigned lo, hi;
        asm("mov.b64 {%0,%1}, %2;" : "=r"(lo), "=r"(hi) : "l"(a01[i]));
        v.x = __uint_as_float(lo); v.y = __uint_as_float(hi);
        asm("mov.b64 {%0,%1}, %2;" : "=r"(lo), "=r"(hi) : "l"(a23[i]));
        v.z = __uint_as_float(lo); v.w = __uint_as_float(hi);
        if (o < QC) {
            float s  = qg[o] * rsqrtf(qv[o] + EPS_BN);
            float sh = qb[o] - qm[o] * s;
            v.x = v.x * s + sh; v.y = v.y * s + sh;
            v.z = v.z * s + sh; v.w = v.w * s + sh;
            *reinterpret_cast<float4*>(&g_q[((size_t)b * QC + o) * MM + m]) = v;
        } else if (o < QC + KC) {
            *reinterpret_cast<float4*>(&g_kraw[((size_t)b * KC + (o - QC)) * MM + m]) = v;
        } else {
            int ov   = o - QC - KC;
            float s  = vg[ov] * rsqrtf(vvr[ov] + EPS_BN);
            float sh = vb[ov] - vm[ov] * s;
            v.x = v.x * s + sh; v.y = v.y * s + sh;
            v.z = v.z * s + sh; v.w = v.w * s + sh;
            *reinterpret_cast<float4*>(&g_vbn[((size_t)b * VC + ov) * MM + m]) = v;
        }
    }
}

// ---------------- K2: softmax over M per (b,k) ------------------------------
__global__ __launch_bounds__(256) void k2_softmax()
{
    const int b = blockIdx.y, k = blockIdx.x;
    const float* src = g_kraw + ((size_t)b * KC + k) * MM;
    float*       dst = g_ksm  + ((size_t)b * KC + k) * MM;
    const int tid = threadIdx.x;
    __shared__ float red[33];

    float mx = -1e30f;
    for (int m = tid; m < MM; m += 256) mx = fmaxf(mx, src[m]);
#pragma unroll
    for (int o = 16; o > 0; o >>= 1) mx = fmaxf(mx, __shfl_xor_sync(0xffffffffu, mx, o));
    if ((tid & 31) == 0) red[tid >> 5] = mx;
    __syncthreads();
    if (tid < 32) {
        float v = (tid < 8) ? red[tid] : -1e30f;
#pragma unroll
        for (int o = 4; o > 0; o >>= 1) v = fmaxf(v, __shfl_xor_sync(0xffffffffu, v, o));
        if (tid == 0) red[0] = v;
    }
    __syncthreads();
    mx = red[0];
    __syncthreads();

    float sm = 0.f;
    for (int m = tid; m < MM; m += 256) sm += expf(src[m] - mx);
#pragma unroll
    for (int o = 16; o > 0; o >>= 1) sm += __shfl_xor_sync(0xffffffffu, sm, o);
    if ((tid & 31) == 0) red[tid >> 5] = sm;
    __syncthreads();
    if (tid < 32) {
        float v = (tid < 8) ? red[tid] : 0.f;
#pragma unroll
        for (int o = 4; o > 0; o >>= 1) v += __shfl_xor_sync(0xffffffffu, v, o);
        if (tid == 0) red[32] = 1.f / v;
    }
    __syncthreads();
    const float inv = red[32];

    for (int m = tid; m < MM; m += 256) dst[m] = expf(src[m] - mx) * inv;
}

// ---------------- K3: lambda_c[b,k,v] = sum_m ksm[b,k,m] * vbn[b,v,m] -------
__global__ __launch_bounds__(256) void k3_lambdac()
{
    const int b = blockIdx.y, v = blockIdx.x;
    const int tid = threadIdx.x;
    const float* vp = g_vbn + ((size_t)b * VC + v) * MM;
    const float* kp = g_ksm + (size_t)b * KC * MM;

    float acc[16];
#pragma unroll
    for (int k = 0; k < 16; k++) acc[k] = 0.f;

    for (int m = tid; m < MM; m += 256) {
        float vv = vp[m];
#pragma unroll
        for (int k = 0; k < 16; k++) acc[k] += kp[(size_t)k * MM + m] * vv;
    }

    __shared__ float part[16][9];
    const int lane = tid & 31, wid = tid >> 5;
#pragma unroll
    for (int k = 0; k < 16; k++) {
        float s = acc[k];
#pragma unroll
        for (int o = 16; o > 0; o >>= 1) s += __shfl_xor_sync(0xffffffffu, s, o);
        if (lane == 0) part[k][wid] = s;
    }
    __syncthreads();
    if (tid < 16) {
        float s = 0.f;
#pragma unroll
        for (int w2 = 0; w2 < 8; w2++) s += part[tid][w2];
        g_lc[((size_t)b * DKK + tid) * DVV + v] = s;
    }
}

// ---------------- K4: fused 23x23 conv + q-contraction ----------------------
// 4 pixels/thread: warp covers 2 rows x 64 cols; block (8 warps) covers 16 rows.
// grid (4 ytiles, 64 v, 8 b), block 256.
__global__ __launch_bounds__(256, 2) void k4_main(
    const float* __restrict__ wl, const float* __restrict__ bl,
    float* __restrict__ out)
{
    __shared__ float s_img[38 * SIMS];                // 16-row tile + 22 halo
    __shared__ __align__(16) float s_w[RR * RR * 16]; // [dy][dx][k], k contiguous
    __shared__ float s_lam[16];

    const int ytile = blockIdx.x;   // 0..3
    const int v     = blockIdx.y;   // 0..63
    const int b     = blockIdx.z;   // 0..7
    const int tid   = threadIdx.x;

    for (int idx = tid; idx < RR * RR * 16; idx += 256) {
        int k = idx & 15;
        int t = idx >> 4;
        s_w[idx] = wl[k * (RR * RR) + t];
    }
    if (tid < 16)
        s_lam[tid] = g_lc[((size_t)b * DKK + tid) * DVV + v] + bl[tid];

    const float* vp = g_vbn + ((size_t)b * VC + v) * MM;
    const int y0 = ytile * 16;
    for (int idx = tid; idx < 38 * SIMS; idx += 256) {
        int r  = idx / SIMS;
        int cc = idx - r * SIMS;
        int gy = y0 + r - PADR;
        int gx = cc - PADR;
        float val = 0.f;
        if (gy >= 0 && gy < HH && gx >= 0 && gx < WW) val = vp[gy * WW + gx];
        s_img[idx] = val;
    }
    __syncthreads();

    const int lane = tid & 31, wid = tid >> 5;
    const int yl = wid * 2 + (lane >> 4);    // local row 0..15
    const int x0 = (lane & 15) * 4;          // 4 adjacent pixels x0..x0+3

    unsigned long long a0[8], a1[8], a2[8], a3[8];
#pragma unroll
    for (int p = 0; p < 8; p++) { a0[p] = 0ull; a1[p] = 0ull; a2[p] = 0ull; a3[p] = 0ull; }

#pragma unroll 1
    for (int dy = 0; dy < RR; dy++) {
        const float*   rowp = &s_img[(yl + dy) * SIMS + x0];
        const double2* wp   = reinterpret_cast<const double2*>(&s_w[dy * RR * 16]);
        unsigned long long vv0 = pack2(rowp[0]);
        unsigned long long vv1 = pack2(rowp[1]);
        unsigned long long vv2 = pack2(rowp[2]);
        unsigned long long vv3 = pack2(rowp[3]);
#pragma unroll
        for (int dx = 0; dx < RR; dx++) {
            unsigned long long vnew = pack2(rowp[dx + 4]);
            double2 wA = wp[dx * 4 + 0];
            double2 wB = wp[dx * 4 + 1];
            double2 wC = wp[dx * 4 + 2];
            double2 wD = wp[dx * 4 + 3];
            unsigned long long w0 = __double_as_longlong(wA.x);
            unsigned long long w1 = __double_as_longlong(wA.y);
            unsigned long long w2 = __double_as_longlong(wB.x);
            unsigned long long w3 = __double_as_longlong(wB.y);
            unsigned long long w4 = __double_as_longlong(wC.x);
            unsigned long long w5 = __double_as_longlong(wC.y);
            unsigned long long w6 = __double_as_longlong(wD.x);
            unsigned long long w7 = __double_as_longlong(wD.y);
            FMA2(a0[0], w0, vv0); FMA2(a1[0], w0, vv1); FMA2(a2[0], w0, vv2); FMA2(a3[0], w0, vv3);
            FMA2(a0[1], w1, vv0); FMA2(a1[1], w1, vv1); FMA2(a2[1], w1, vv2); FMA2(a3[1], w1, vv3);
            FMA2(a0[2], w2, vv0); FMA2(a1[2], w2, vv1); FMA2(a2[2], w2, vv2); FMA2(a3[2], w2, vv3);
            FMA2(a0[3], w3, vv0); FMA2(a1[3], w3, vv1); FMA2(a2[3], w3, vv2); FMA2(a3[3], w3, vv3);
            FMA2(a0[4], w4, vv0); FMA2(a1[4], w4, vv1); FMA2(a2[4], w4, vv2); FMA2(a3[4], w4, vv3);
            FMA2(a0[5], w5, vv0); FMA2(a1[5], w5, vv1); FMA2(a2[5], w5, vv2); FMA2(a3[5], w5, vv3);
            FMA2(a0[6], w6, vv0); FMA2(a1[6], w6, vv1); FMA2(a2[6], w6, vv2); FMA2(a3[6], w6, vv3);
            FMA2(a0[7], w7, vv0); FMA2(a1[7], w7, vv1); FMA2(a2[7], w7, vv2); FMA2(a3[7], w7, vv3);
            vv0 = vv1; vv1 = vv2; vv2 = vv3; vv3 = vnew;
        }
    }

    // epilogue: unpack conv accumulators, add lambda_c + b_lambda, contract with q
    float lam0[16], lam1[16], lam2[16], lam3[16];
#pragma unroll
    for (int p = 0; p < 8; p++) {
        unsigned lo, hi;
        asm("mov.b64 {%0,%1}, %2;" : "=r"(lo), "=r"(hi) : "l"(a0[p]));
        lam0[2*p] = __uint_as_float(lo) + s_lam[2*p]; lam0[2*p+1] = __uint_as_float(hi) + s_lam[2*p+1];
        asm("mov.b64 {%0,%1}, %2;" : "=r"(lo), "=r"(hi) : "l"(a1[p]));
        lam1[2*p] = __uint_as_float(lo) + s_lam[2*p]; lam1[2*p+1] = __uint_as_float(hi) + s_lam[2*p+1];
        asm("mov.b64 {%0,%1}, %2;" : "=r"(lo), "=r"(hi) : "l"(a2[p]));
        lam2[2*p] = __uint_as_float(lo) + s_lam[2*p]; lam2[2*p+1] = __uint_as_float(hi) + s_lam[2*p+1];
        asm("mov.b64 {%0,%1}, %2;" : "=r"(lo), "=r"(hi) : "l"(a3[p]));
        lam3[2*p] = __uint_as_float(lo) + s_lam[2*p]; lam3[2*p+1] = __uint_as_float(hi) + s_lam[2*p+1];
    }

    const int m0 = (y0 + yl) * WW + x0;
    const float* qb_ = g_q + (size_t)b * QC * MM;
    float*       ob  = out + (size_t)b * DIM * MM;
#pragma unroll
    for (int h = 0; h < NHD; h++) {
        float4 s = make_float4(0.f, 0.f, 0.f, 0.f);
#pragma unroll
        for (int k = 0; k < 16; k++) {
            float4 qv = *reinterpret_cast<const float4*>(qb_ + (size_t)(h * 16 + k) * MM + m0);
            s.x += qv.x * lam0[k];
            s.y += qv.y * lam1[k];
            s.z += qv.z * lam2[k];
            s.w += qv.w * lam3[k];
        }
        *reinterpret_cast<float4*>(&ob[(size_t)(h * DVV + v) * MM + m0]) = s;
    }
}

// ---------------- launch ----------------------------------------------------
extern "C" void kernel_launch(void* const* d_in, const int* in_sizes, int n_in,
                              void* d_out, int out_size)
{
    const float* x    = (const float*)d_in[0];
    const float* wq   = (const float*)d_in[1];
    const float* qg   = (const float*)d_in[2];
    const float* qb   = (const float*)d_in[3];
    const float* qm   = (const float*)d_in[4];
    const float* qv   = (const float*)d_in[5];
    const float* vg   = (const float*)d_in[6];
    const float* vb   = (const float*)d_in[7];
    const float* vm   = (const float*)d_in[8];
    const float* vvr  = (const float*)d_in[9];
    const float* wl   = (const float*)d_in[10];
    const float* bl   = (const float*)d_in[11];
    float*       out  = (float*)d_out;

    dim3 g1(MM / 64, BATCH);
    k1_qkv<<<g1, 256>>>(x, wq, qg, qb, qm, qv, vg, vb, vm, vvr);

    dim3 g2(KC, BATCH);
    k2_softmax<<<g2, 256>>>();

    dim3 g3(DVV, BATCH);
    k3_lambdac<<<g3, 256>>>();

    dim3 g4(4, DVV, BATCH);
    k4_main<<<g4, 256>>>(wl, bl, out);
}

// round 4
// speedup vs baseline: 1.0116x; 1.0008x over previous
#include <cuda_runtime.h>
#include <math.h>

#define BATCH 8
#define DIM   256
#define HH    64
#define WW    64
#define MM    4096
#define QC    64
#define KC    16
#define VC    64
#define NHD   4
#define DKK   16
#define DVV   64
#define RR    23
#define PADR  11
#define EPS_BN 1e-5f

#define SIMS  89   // s_img row stride (odd offset => fewer bank conflicts)

// ---------------- scratch (device globals: no allocations allowed) ----------
__device__ float g_q   [BATCH*QC*MM];   // BN'd q, layout [b][o=h*16+k][m]
__device__ float g_kraw[BATCH*KC*MM];   // raw k logits
__device__ float g_vbn [BATCH*VC*MM];   // BN'd v
__device__ float g_ksm [BATCH*KC*MM];   // softmax(k) over M
__device__ float g_lc  [BATCH*DKK*DVV]; // lambda_c[b][k][v]

// ---------------- packed f32x2 helpers --------------------------------------
__device__ __forceinline__ unsigned long long pack2(float f)
{
    unsigned long long r;
    unsigned u = __float_as_uint(f);
    asm("mov.b64 %0, {%1,%2};" : "=l"(r) : "r"(u), "r"(u));
    return r;
}
__device__ __forceinline__ unsigned long long packab(float a, float b)
{
    unsigned long long r;
    asm("mov.b64 %0, {%1,%2};" : "=l"(r)
        : "r"(__float_as_uint(a)), "r"(__float_as_uint(b)));
    return r;
}
#define FMA2(a, w, v) asm("fma.rn.f32x2 %0, %1, %2, %0;" : "+l"(a) : "l"(w), "l"(v))

// ---------------- K1: QKV GEMM + fused BN (f32x2 inner) ---------------------
// per batch: Y[144,4096] = W[144,256] @ X[256,4096]
// grid (64 mtiles, 8 b), block 256.  tile = 144 o x 64 m.
__global__ __launch_bounds__(256) void k1_qkv(
    const float* __restrict__ x, const float* __restrict__ w,
    const float* __restrict__ qg, const float* __restrict__ qb,
    const float* __restrict__ qm, const float* __restrict__ qv,
    const float* __restrict__ vg, const float* __restrict__ vb,
    const float* __restrict__ vm, const float* __restrict__ vvr)
{
    __shared__ float Xs[32][64];
    __shared__ float Ws[32][144];
    const int b     = blockIdx.y;
    const int mtile = blockIdx.x * 64;
    const int tid   = threadIdx.x;
    const int mg    = tid & 15;   // 16 m-groups (4 m each)
    const int og    = tid >> 4;   // 16 o-groups (o = og + 16*i)

    unsigned long long a01[9], a23[9];
#pragma unroll
    for (int i = 0; i < 9; i++) { a01[i] = 0ull; a23[i] = 0ull; }

    const float* xb = x + (size_t)b * DIM * MM + mtile;

    for (int c0 = 0; c0 < DIM; c0 += 32) {
        {
            int L  = tid * 8;
            int cc = L >> 6;
            int ml = L & 63;
            const float* src = xb + (size_t)(c0 + cc) * MM + ml;
            *reinterpret_cast<float4*>(&Xs[cc][ml])     = *reinterpret_cast<const float4*>(src);
            *reinterpret_cast<float4*>(&Xs[cc][ml + 4]) = *reinterpret_cast<const float4*>(src + 4);
        }
        for (int idx = tid; idx < 32 * 144; idx += 256) {
            int cc = idx / 144;
            int o  = idx - cc * 144;
            Ws[cc][o] = w[o * DIM + c0 + cc];
        }
        __syncthreads();
#pragma unroll
        for (int cc = 0; cc < 32; cc++) {
            float4 xv = *reinterpret_cast<const float4*>(&Xs[cc][mg * 4]);
            unsigned long long xv01 = packab(xv.x, xv.y);
            unsigned long long xv23 = packab(xv.z, xv.w);
#pragma unroll
            for (int i = 0; i < 9; i++) {
                unsigned long long wv = pack2(Ws[cc][og + 16 * i]);
                FMA2(a01[i], wv, xv01);
                FMA2(a23[i], wv, xv23);
            }
        }
        __syncthreads();
    }

    const int m = mtile + mg * 4;
#pragma unroll
    for (int i = 0; i < 9; i++) {
        int o = og + 16 * i;
        float4 v;
        unsigned lo, hi;
        asm("mov.b64 {%0,%1}, %2;" : "=r"(lo), "=r"(hi) : "l"(a01[i]));
        v.x = __uint_as_float(lo); v.y = __uint_as_float(hi);
        asm("mov.b64 {%0,%1}, %2;" : "=r"(lo), "=r"(hi) : "l"(a23[i]));
        v.z = __uint_as_float(lo); v.w = __uint_as_float(hi);
        if (o < QC) {
            float s  = qg[o] * rsqrtf(qv[o] + EPS_BN);
            float sh = qb[o] - qm[o] * s;
            v.x = v.x * s + sh; v.y = v.y * s + sh;
            v.z = v.z * s + sh; v.w = v.w * s + sh;
            *reinterpret_cast<float4*>(&g_q[((size_t)b * QC + o) * MM + m]) = v;
        } else if (o < QC + KC) {
            *reinterpret_cast<float4*>(&g_kraw[((size_t)b * KC + (o - QC)) * MM + m]) = v;
        } else {
            int ov   = o - QC - KC;
            float s  = vg[ov] * rsqrtf(vvr[ov] + EPS_BN);
            float sh = vb[ov] - vm[ov] * s;
            v.x = v.x * s + sh; v.y = v.y * s + sh;
            v.z = v.z * s + sh; v.w = v.w * s + sh;
            *reinterpret_cast<float4*>(&g_vbn[((size_t)b * VC + ov) * MM + m]) = v;
        }
    }
}

// ---------------- K2: softmax over M per (b,k) ------------------------------
__global__ __launch_bounds__(256) void k2_softmax()
{
    const int b = blockIdx.y, k = blockIdx.x;
    const float* src = g_kraw + ((size_t)b * KC + k) * MM;
    float*       dst = g_ksm  + ((size_t)b * KC + k) * MM;
    const int tid = threadIdx.x;
    __shared__ float red[33];

    float mx = -1e30f;
    for (int m = tid; m < MM; m += 256) mx = fmaxf(mx, src[m]);
#pragma unroll
    for (int o = 16; o > 0; o >>= 1) mx = fmaxf(mx, __shfl_xor_sync(0xffffffffu, mx, o));
    if ((tid & 31) == 0) red[tid >> 5] = mx;
    __syncthreads();
    if (tid < 32) {
        float v = (tid < 8) ? red[tid] : -1e30f;
#pragma unroll
        for (int o = 4; o > 0; o >>= 1) v = fmaxf(v, __shfl_xor_sync(0xffffffffu, v, o));
        if (tid == 0) red[0] = v;
    }
    __syncthreads();
    mx = red[0];
    __syncthreads();

    float sm = 0.f;
    for (int m = tid; m < MM; m += 256) sm += expf(src[m] - mx);
#pragma unroll
    for (int o = 16; o > 0; o >>= 1) sm += __shfl_xor_sync(0xffffffffu, sm, o);
    if ((tid & 31) == 0) red[tid >> 5] = sm;
    __syncthreads();
    if (tid < 32) {
        float v = (tid < 8) ? red[tid] : 0.f;
#pragma unroll
        for (int o = 4; o > 0; o >>= 1) v += __shfl_xor_sync(0xffffffffu, v, o);
        if (tid == 0) red[32] = 1.f / v;
    }
    __syncthreads();
    const float inv = red[32];

    for (int m = tid; m < MM; m += 256) dst[m] = expf(src[m] - mx) * inv;
}

// ---------------- K3: lambda_c[b,k,v] = sum_m ksm[b,k,m] * vbn[b,v,m] -------
__global__ __launch_bounds__(256) void k3_lambdac()
{
    const int b = blockIdx.y, v = blockIdx.x;
    const int tid = threadIdx.x;
    const float* vp = g_vbn + ((size_t)b * VC + v) * MM;
    const float* kp = g_ksm + (size_t)b * KC * MM;

    float acc[16];
#pragma unroll
    for (int k = 0; k < 16; k++) acc[k] = 0.f;

    for (int m = tid; m < MM; m += 256) {
        float vv = vp[m];
#pragma unroll
        for (int k = 0; k < 16; k++) acc[k] += kp[(size_t)k * MM + m] * vv;
    }

    __shared__ float part[16][9];
    const int lane = tid & 31, wid = tid >> 5;
#pragma unroll
    for (int k = 0; k < 16; k++) {
        float s = acc[k];
#pragma unroll
        for (int o = 16; o > 0; o >>= 1) s += __shfl_xor_sync(0xffffffffu, s, o);
        if (lane == 0) part[k][wid] = s;
    }
    __syncthreads();
    if (tid < 16) {
        float s = 0.f;
#pragma unroll
        for (int w2 = 0; w2 < 8; w2++) s += part[tid][w2];
        g_lc[((size_t)b * DKK + tid) * DVV + v] = s;
    }
}

// ---------------- K4: fused 23x23 conv + q-contraction ----------------------
// 4 pixels/thread: warp covers 2 rows x 64 cols; block (8 warps) covers 16 rows.
// grid (4 ytiles, 64 v, 8 b), block 256.
__global__ __launch_bounds__(256, 2) void k4_main(
    const float* __restrict__ wl, const float* __restrict__ bl,
    float* __restrict__ out)
{
    __shared__ float s_img[38 * SIMS];                // 16-row tile + 22 halo
    __shared__ __align__(16) float s_w[RR * RR * 16]; // [dy][dx][k], k contiguous
    __shared__ float s_lam[16];

    const int ytile = blockIdx.x;   // 0..3
    const int v     = blockIdx.y;   // 0..63
    const int b     = blockIdx.z;   // 0..7
    const int tid   = threadIdx.x;

    for (int idx = tid; idx < RR * RR * 16; idx += 256) {
        int k = idx & 15;
        int t = idx >> 4;
        s_w[idx] = wl[k * (RR * RR) + t];
    }
    if (tid < 16)
        s_lam[tid] = g_lc[((size_t)b * DKK + tid) * DVV + v] + bl[tid];

    const float* vp = g_vbn + ((size_t)b * VC + v) * MM;
    const int y0 = ytile * 16;
    for (int idx = tid; idx < 38 * SIMS; idx += 256) {
        int r  = idx / SIMS;
        int cc = idx - r * SIMS;
        int gy = y0 + r - PADR;
        int gx = cc - PADR;
        float val = 0.f;
        if (gy >= 0 && gy < HH && gx >= 0 && gx < WW) val = vp[gy * WW + gx];
        s_img[idx] = val;
    }
    __syncthreads();

    const int lane = tid & 31, wid = tid >> 5;
    const int yl = wid * 2 + (lane >> 4);    // local row 0..15
    const int x0 = (lane & 15) * 4;          // 4 adjacent pixels x0..x0+3

    unsigned long long a0[8], a1[8], a2[8], a3[8];
#pragma unroll
    for (int p = 0; p < 8; p++) { a0[p] = 0ull; a1[p] = 0ull; a2[p] = 0ull; a3[p] = 0ull; }

#pragma unroll 1
    for (int dy = 0; dy < RR; dy++) {
        const float*   rowp = &s_img[(yl + dy) * SIMS + x0];
        const double2* wp   = reinterpret_cast<const double2*>(&s_w[dy * RR * 16]);
        unsigned long long vv0 = pack2(rowp[0]);
        unsigned long long vv1 = pack2(rowp[1]);
        unsigned long long vv2 = pack2(rowp[2]);
        unsigned long long vv3 = pack2(rowp[3]);
#pragma unroll
        for (int dx = 0; dx < RR; dx++) {
            unsigned long long vnew = pack2(rowp[dx + 4]);
            double2 wA = wp[dx * 4 + 0];
            double2 wB = wp[dx * 4 + 1];
            double2 wC = wp[dx * 4 + 2];
            double2 wD = wp[dx * 4 + 3];
            unsigned long long w0 = __double_as_longlong(wA.x);
            unsigned long long w1 = __double_as_longlong(wA.y);
            unsigned long long w2 = __double_as_longlong(wB.x);
            unsigned long long w3 = __double_as_longlong(wB.y);
            unsigned long long w4 = __double_as_longlong(wC.x);
            unsigned long long w5 = __double_as_longlong(wC.y);
            unsigned long long w6 = __double_as_longlong(wD.x);
            unsigned long long w7 = __double_as_longlong(wD.y);
            FMA2(a0[0], w0, vv0); FMA2(a1[0], w0, vv1); FMA2(a2[0], w0, vv2); FMA2(a3[0], w0, vv3);
            FMA2(a0[1], w1, vv0); FMA2(a1[1], w1, vv1); FMA2(a2[1], w1, vv2); FMA2(a3[1], w1, vv3);
            FMA2(a0[2], w2, vv0); FMA2(a1[2], w2, vv1); FMA2(a2[2], w2, vv2); FMA2(a3[2], w2, vv3);
            FMA2(a0[3], w3, vv0); FMA2(a1[3], w3, vv1); FMA2(a2[3], w3, vv2); FMA2(a3[3], w3, vv3);
            FMA2(a0[4], w4, vv0); FMA2(a1[4], w4, vv1); FMA2(a2[4], w4, vv2); FMA2(a3[4], w4, vv3);
            FMA2(a0[5], w5, vv0); FMA2(a1[5], w5, vv1); FMA2(a2[5], w5, vv2); FMA2(a3[5], w5, vv3);
            FMA2(a0[6], w6, vv0); FMA2(a1[6], w6, vv1); FMA2(a2[6], w6, vv2); FMA2(a3[6], w6, vv3);
            FMA2(a0[7], w7, vv0); FMA2(a1[7], w7, vv1); FMA2(a2[7], w7, vv2); FMA2(a3[7], w7, vv3);
            vv0 = vv1; vv1 = vv2; vv2 = vv3; vv3 = vnew;
        }
    }

    // epilogue: unpack conv accumulators, add lambda_c + b_lambda, contract with q
    float lam0[16], lam1[16], lam2[16], lam3[16];
#pragma unroll
    for (int p = 0; p < 8; p++) {
        unsigned lo, hi;
        asm("mov.b64 {%0,%1}, %2;" : "=r"(lo), "=r"(hi) : "l"(a0[p]));
        lam0[2*p] = __uint_as_float(lo) + s_lam[2*p]; lam0[2*p+1] = __uint_as_float(hi) + s_lam[2*p+1];
        asm("mov.b64 {%0,%1}, %2;" : "=r"(lo), "=r"(hi) : "l"(a1[p]));
        lam1[2*p] = __uint_as_float(lo) + s_lam[2*p]; lam1[2*p+1] = __uint_as_float(hi) + s_lam[2*p+1];
        asm("mov.b64 {%0,%1}, %2;" : "=r"(lo), "=r"(hi) : "l"(a2[p]));
        lam2[2*p] = __uint_as_float(lo) + s_lam[2*p]; lam2[2*p+1] = __uint_as_float(hi) + s_lam[2*p+1];
        asm("mov.b64 {%0,%1}, %2;" : "=r"(lo), "=r"(hi) : "l"(a3[p]));
        lam3[2*p] = __uint_as_float(lo) + s_lam[2*p]; lam3[2*p+1] = __uint_as_float(hi) + s_lam[2*p+1];
    }

    const int m0 = (y0 + yl) * WW + x0;
    const float* qb_ = g_q + (size_t)b * QC * MM;
    float*       ob  = out + (size_t)b * DIM * MM;
#pragma unroll
    for (int h = 0; h < NHD; h++) {
        float4 s = make_float4(0.f, 0.f, 0.f, 0.f);
#pragma unroll
        for (int k = 0; k < 16; k++) {
            float4 qv = *reinterpret_cast<const float4*>(qb_ + (size_t)(h * 16 + k) * MM + m0);
            s.x += qv.x * lam0[k];
            s.y += qv.y * lam1[k];
            s.z += qv.z * lam2[k];
            s.w += qv.w * lam3[k];
        }
        *reinterpret_cast<float4*>(&ob[(size_t)(h * DVV + v) * MM + m0]) = s;
    }
}

// ---------------- launch ----------------------------------------------------
extern "C" void kernel_launch(void* const* d_in, const int* in_sizes, int n_in,
                              void* d_out, int out_size)
{
    const float* x    = (const float*)d_in[0];
    const float* wq   = (const float*)d_in[1];
    const float* qg   = (const float*)d_in[2];
    const float* qb   = (const float*)d_in[3];
    const float* qm   = (const float*)d_in[4];
    const float* qv   = (const float*)d_in[5];
    const float* vg   = (const float*)d_in[6];
    const float* vb   = (const float*)d_in[7];
    const float* vm   = (const float*)d_in[8];
    const float* vvr  = (const float*)d_in[9];
    const float* wl   = (const float*)d_in[10];
    const float* bl   = (const float*)d_in[11];
    float*       out  = (float*)d_out;

    dim3 g1(MM / 64, BATCH);
    k1_qkv<<<g1, 256>>>(x, wq, qg, qb, qm, qv, vg, vb, vm, vvr);

    dim3 g2(KC, BATCH);
    k2_softmax<<<g2, 256>>>();

    dim3 g3(DVV, BATCH);
    k3_lambdac<<<g3, 256>>>();

    dim3 g4(4, DVV, BATCH);
    k4_main<<<g4, 256>>>(wl, bl, out);
}